// round 7
// baseline (speedup 1.0000x reference)
#include <cuda_runtime.h>
#include <cuda_bf16.h>
#include <cstdint>
#include <cstddef>

#define NB 128
#define NT 2048
#define NS 64
#define AGG_STR 65
#define BG_STR  66

// ---------------- device scratch ----------------
__device__ unsigned int d_hA[(size_t)NB * 64 * 2048];
__device__ unsigned int d_hB[(size_t)NB * 64 * 2048];
__device__ unsigned int d_agg0[(size_t)NB * 4096];
__device__ unsigned int d_agg1[(size_t)NB * 4096];
__device__ unsigned int d_agg2[(size_t)NB * 4096];
__device__ int d_is32;          // .bss zero-init; monotone set, idempotent across replays

// ---------------- helpers ----------------
__device__ __forceinline__ void bsplit(float v, uint32_t& h, uint32_t& l) {
    __nv_bfloat16 bh = __float2bfloat16(v);
    __nv_bfloat16 bl = __float2bfloat16(v - __bfloat162float(bh));
    h = (uint32_t)__bfloat16_as_ushort(bh);
    l = (uint32_t)__bfloat16_as_ushort(bl);
}
__device__ __forceinline__ uint32_t packbf(uint32_t lo16, uint32_t hi16) {
    return lo16 | (hi16 << 16);
}
__device__ __forceinline__ void mma16816(float* d, uint32_t a0, uint32_t a1,
                                         uint32_t a2, uint32_t a3,
                                         uint32_t b0, uint32_t b1) {
    asm volatile(
        "mma.sync.aligned.m16n8k16.row.col.f32.bf16.bf16.f32 "
        "{%0,%1,%2,%3}, {%4,%5,%6,%7}, {%8,%9}, {%0,%1,%2,%3};"
        : "+f"(d[0]), "+f"(d[1]), "+f"(d[2]), "+f"(d[3])
        : "r"(a0), "r"(a1), "r"(a2), "r"(a3), "r"(b0), "r"(b1));
}

// ---------------- prep: zero agg buffers + dtype sniff ----------------
__global__ void k_prep(const int* __restrict__ cl) {
    const int i = blockIdx.x * blockDim.x + threadIdx.x;   // 1024*512 = 524288
    if (i < NB * 4096) { d_agg0[i] = 0u; d_agg1[i] = 0u; d_agg2[i] = 0u; }
    const int idx = 2 * i + 1;
    if (idx < NB * NT) { if (cl[idx] != 0) d_is32 = 1; }
}

// ---------------- half-tile epilogue: +BG, LN, affine, ReLU, agg, frag-store ----------------
// acc[nt][q]: q0=(row g+16*half, col 2tg of nt), q1=col+1, q2=(row g+8+16*half), q3=odd
template <bool SEGBG, bool STORE>
__device__ __forceinline__ void epilogue_half(
    float (&acc)[8][4], int seg0, int seg1, int half,
    const char* bgTab, const float4* sGBp, unsigned* sAgg,
    int lane, uint4* dst)
{
    const int tg = lane & 3;
    if (SEGBG) {
        const float* sBG = (const float*)bgTab;
        const float* r0 = sBG + seg0 * BG_STR + tg * 2;
        const float* r1 = sBG + seg1 * BG_STR + tg * 2;
        #pragma unroll
        for (int nt = 0; nt < 8; nt++) {
            float2 b0 = *(const float2*)(r0 + nt * 8);
            float2 b1 = *(const float2*)(r1 + nt * 8);
            acc[nt][0] += b0.x; acc[nt][1] += b0.y;
            acc[nt][2] += b1.x; acc[nt][3] += b1.y;
        }
    } else {
        const float2* sB0 = (const float2*)bgTab;
        #pragma unroll
        for (int nt = 0; nt < 8; nt++) {
            float2 bb = sB0[nt * 4 + tg];
            acc[nt][0] += bb.x; acc[nt][1] += bb.y;
            acc[nt][2] += bb.x; acc[nt][3] += bb.y;
        }
    }
    float mu[2], rs[2];
    #pragma unroll
    for (int rh = 0; rh < 2; rh++) {
        float s = 0.f;
        #pragma unroll
        for (int nt = 0; nt < 8; nt++) s += acc[nt][rh * 2] + acc[nt][rh * 2 + 1];
        s += __shfl_xor_sync(0xffffffffu, s, 1);
        s += __shfl_xor_sync(0xffffffffu, s, 2);
        mu[rh] = s * (1.0f / 64.0f);
        float q = 0.f;
        #pragma unroll
        for (int nt = 0; nt < 8; nt++) {
            float d0 = acc[nt][rh * 2]     - mu[rh];
            float d1 = acc[nt][rh * 2 + 1] - mu[rh];
            q = fmaf(d0, d0, q); q = fmaf(d1, d1, q);
        }
        q += __shfl_xor_sync(0xffffffffu, q, 1);
        q += __shfl_xor_sync(0xffffffffu, q, 2);
        rs[rh] = rsqrtf(q * (1.0f / 64.0f) + 1e-5f);
    }
    const int sg[2] = {seg0, seg1};
    #pragma unroll
    for (int ntp = 0; ntp < 4; ntp++) {
        uint32_t hi4[4], lo4[4];
        #pragma unroll
        for (int q2 = 0; q2 < 2; q2++) {
            const int nt = 2 * ntp + q2;
            float4 gb = sGBp[nt * 4 + tg];
            const int c0 = nt * 8 + tg * 2;
            #pragma unroll
            for (int rh = 0; rh < 2; rh++) {
                float v0 = fmaxf(fmaf((acc[nt][rh * 2]     - mu[rh]) * rs[rh], gb.x, gb.y), 0.f);
                float v1 = fmaxf(fmaf((acc[nt][rh * 2 + 1] - mu[rh]) * rs[rh], gb.z, gb.w), 0.f);
                uint32_t u0 = __float_as_uint(v0), u1 = __float_as_uint(v1);
                unsigned* s0 = &sAgg[sg[rh] * AGG_STR + c0];
                if (u0 > s0[0]) atomicMax(s0,     u0);
                if (u1 > s0[1]) atomicMax(s0 + 1, u1);
                if (STORE) {
                    uint32_t h0, l0, h1, l1;
                    bsplit(v0, h0, l0); bsplit(v1, h1, l1);
                    hi4[q2 * 2 + rh] = packbf(h0, h1);
                    lo4[q2 * 2 + rh] = packbf(l0, l1);
                }
            }
        }
        if (STORE) {
            dst[(half * 4 + ntp) * 32 + lane]     = *(uint4*)hi4;
            dst[(8 + half * 4 + ntp) * 32 + lane] = *(uint4*)lo4;
        }
    }
}

// ---------------- layer 0: scalar K=8, 4 CTAs per batch ----------------
#define L0_W0P 0        // 256 float2 = 2048
#define L0_GBP 2048     // 32 float4 = 512
#define L0_B0  2560     // 32 float2 = 256
#define L0_AGG 2816     // 65*64*4 = 16640
#define L0_CL  19456    // 512
#define L0_SMEM 19968

__global__ __launch_bounds__(256, 3)
void k_l0(const float* __restrict__ x, const void* __restrict__ clraw,
          const float* __restrict__ W0, const float* __restrict__ bs0,
          const float* __restrict__ gm0, const float* __restrict__ bt0)
{
    __shared__ __align__(16) char sm[L0_SMEM];
    float2*        sW0p = (float2*)(sm + L0_W0P);
    float4*        sGBp = (float4*)(sm + L0_GBP);
    float2*        sB0  = (float2*)(sm + L0_B0);
    unsigned*      sAgg = (unsigned*)(sm + L0_AGG);
    unsigned char* sCl  = (unsigned char*)(sm + L0_CL);

    const int cta = blockIdx.x, b = cta >> 2, qr = cta & 3;
    const int tid = threadIdx.x, lane = tid & 31, warp = tid >> 5;
    const int tg = lane & 3, g = lane >> 2;

    {
        const int is32 = d_is32;
        const int* c32 = (const int*)clraw;
        const long long* c64 = (const long long*)clraw;
        for (int i = tid; i < 512; i += 256) {
            size_t gi = (size_t)b * NT + qr * 512 + i;
            sCl[i] = (unsigned char)(is32 ? c32[gi] : (int)c64[gi]);
        }
    }
    {   // W0 frag-col order: one entry per thread
        const int k = tid >> 5, nt = (tid >> 2) & 7, tg2 = tid & 3;
        const int c0 = nt * 8 + tg2 * 2;
        sW0p[tid] = make_float2(W0[k * 64 + c0], W0[k * 64 + c0 + 1]);
    }
    if (tid < 32) {
        const int nt = tid >> 2, tg2 = tid & 3, c0 = nt * 8 + tg2 * 2;
        sGBp[tid] = make_float4(gm0[c0], bt0[c0], gm0[c0 + 1], bt0[c0 + 1]);
        sB0[tid]  = make_float2(bs0[c0], bs0[c0 + 1]);
    }
    for (int i = tid; i < NS * AGG_STR; i += 256) sAgg[i] = 0u;
    __syncthreads();

    for (int pass = 0; pass < 2; pass++) {
        const int tile = qr * 16 + pass * 8 + warp;
        const int tloc = (pass * 8 + warp) * 32;
        int segs[4];
        #pragma unroll
        for (int r = 0; r < 4; r++) segs[r] = sCl[tloc + g + 8 * r];
        uint4* dst = (uint4*)(d_hA + ((size_t)b * 64 + tile) * 2048);

        #pragma unroll
        for (int half = 0; half < 2; half++) {
            float xr[2][8];
            #pragma unroll
            for (int rh = 0; rh < 2; rh++) {
                const int row = g + 16 * half + 8 * rh;
                const float4* xp = (const float4*)(x + ((size_t)b * NT + qr * 512 + tloc + row) * 8);
                float4 xa = __ldg(xp), xb = __ldg(xp + 1);
                xr[rh][0] = xa.x; xr[rh][1] = xa.y; xr[rh][2] = xa.z; xr[rh][3] = xa.w;
                xr[rh][4] = xb.x; xr[rh][5] = xb.y; xr[rh][6] = xb.z; xr[rh][7] = xb.w;
            }
            float acc[8][4];
            #pragma unroll
            for (int nt = 0; nt < 8; nt++)
                #pragma unroll
                for (int q = 0; q < 4; q++) acc[nt][q] = 0.f;
            #pragma unroll
            for (int k = 0; k < 8; k++) {
                #pragma unroll
                for (int nt = 0; nt < 8; nt++) {
                    float2 w = sW0p[(k * 8 + nt) * 4 + tg];
                    acc[nt][0] = fmaf(xr[0][k], w.x, acc[nt][0]);
                    acc[nt][1] = fmaf(xr[0][k], w.y, acc[nt][1]);
                    acc[nt][2] = fmaf(xr[1][k], w.x, acc[nt][2]);
                    acc[nt][3] = fmaf(xr[1][k], w.y, acc[nt][3]);
                }
            }
            epilogue_half<false, true>(acc, segs[half * 2], segs[half * 2 + 1], half,
                                       (const char*)sB0, sGBp, sAgg, lane, dst);
        }
    }
    __syncthreads();
    unsigned* gA = d_agg0 + (size_t)b * 4096;
    for (int i = tid; i < 4096; i += 256) {
        unsigned v = sAgg[(i >> 6) * AGG_STR + (i & 63)];
        if (v > gA[i]) atomicMax(&gA[i], v);
    }
}

// ---------------- layers 1,2: bf16 hi/lo mma, 4 CTAs per batch ----------------
#define LT_HI  0        // 2048 uint2 = 16384
#define LT_LO  16384
#define LT_BG  32768    // 66*64*4 = 16896
#define LT_AGG 49664    // 65*64*4 = 16640 (first 16384B doubles as Wbot stage)
#define LT_GBP 66304    // 512
#define LT_CL  66816    // 512
#define LT_SMEM 67328

template <int L>
__global__ __launch_bounds__(256, 3)
void k_lmma(const void* __restrict__ clraw,
            const float* __restrict__ W, const float* __restrict__ bs,
            const float* __restrict__ gm, const float* __restrict__ bt)
{
    extern __shared__ __align__(16) char sm[];
    uint2*         sBfHi = (uint2*)(sm + LT_HI);
    uint2*         sBfLo = (uint2*)(sm + LT_LO);
    float*         sBG   = (float*)(sm + LT_BG);
    unsigned*      sAgg  = (unsigned*)(sm + LT_AGG);
    float4*        sGBp  = (float4*)(sm + LT_GBP);
    unsigned char* sCl   = (unsigned char*)(sm + LT_CL);

    const int cta = blockIdx.x, b = cta >> 2, qr = cta & 3;
    const int tid = threadIdx.x, lane = tid & 31, warp = tid >> 5;
    const int g = lane >> 2;

    // stage Wbot into (future) sAgg region
    float* stage = (float*)(sm + LT_AGG);
    for (int i = tid; i < 4096; i += 256) stage[i] = W[4096 + i];
    // W top frags hi/lo
    for (int i = tid; i < 2048; i += 256) {
        const int l2 = i & 31, nt = (i >> 5) & 7, kt = i >> 8;
        const int tg2 = l2 & 3, g2 = l2 >> 2;
        const int k0 = kt * 16 + tg2 * 2, n = nt * 8 + g2;
        uint32_t h00, l00, h01, l01, h10, l10, h11, l11;
        bsplit(W[k0 * 64 + n], h00, l00);       bsplit(W[(k0 + 1) * 64 + n], h01, l01);
        bsplit(W[(k0 + 8) * 64 + n], h10, l10); bsplit(W[(k0 + 9) * 64 + n], h11, l11);
        sBfHi[i] = make_uint2(packbf(h00, h01), packbf(h10, h11));
        sBfLo[i] = make_uint2(packbf(l00, l01), packbf(l10, l11));
    }
    if (tid < 32) {
        const int nt = tid >> 2, tg2 = tid & 3, c0 = nt * 8 + tg2 * 2;
        sGBp[tid] = make_float4(gm[c0], bt[c0], gm[c0 + 1], bt[c0 + 1]);
    }
    {
        const int is32 = d_is32;
        const int* c32 = (const int*)clraw;
        const long long* c64 = (const long long*)clraw;
        for (int i = tid; i < 512; i += 256) {
            size_t gi = (size_t)b * NT + qr * 512 + i;
            sCl[i] = (unsigned char)(is32 ? c32[gi] : (int)c64[gi]);
        }
    }
    __syncthreads();

    // BG = bias + aggPrev @ Wbot (Wbot from smem stage)
    {
        const unsigned* aggP = (L == 1 ? d_agg0 : d_agg1) + (size_t)b * 4096;
        const int seg = tid >> 2, f0 = (tid & 3) * 16;
        float a16[16];
        #pragma unroll
        for (int j = 0; j < 16; j++) a16[j] = 0.f;
        #pragma unroll 4
        for (int k = 0; k < 64; k++) {
            float av = __uint_as_float(__ldg(&aggP[seg * 64 + k]));
            const float* wr = stage + k * 64 + f0;
            #pragma unroll
            for (int j = 0; j < 16; j += 4) {
                float4 w = *(const float4*)(wr + j);
                a16[j]   = fmaf(av, w.x, a16[j]);
                a16[j+1] = fmaf(av, w.y, a16[j+1]);
                a16[j+2] = fmaf(av, w.z, a16[j+2]);
                a16[j+3] = fmaf(av, w.w, a16[j+3]);
            }
        }
        float* bgrow = sBG + seg * BG_STR + f0;
        #pragma unroll
        for (int j = 0; j < 16; j++) bgrow[j] = bs[f0 + j] + a16[j];
    }
    __syncthreads();
    for (int i = tid; i < NS * AGG_STR; i += 256) sAgg[i] = 0u;
    __syncthreads();

    const unsigned int* hsrc = (L == 1 ? d_hA : d_hB);
    for (int pass = 0; pass < 2; pass++) {
        const int tile = qr * 16 + pass * 8 + warp;
        const int tloc = (pass * 8 + warp) * 32;
        const uint4* src = (const uint4*)(hsrc + ((size_t)b * 64 + tile) * 2048);
        int segs[4];
        #pragma unroll
        for (int r = 0; r < 4; r++) segs[r] = sCl[tloc + g + 8 * r];
        uint4* dst = (L == 1) ? (uint4*)(d_hB + ((size_t)b * 64 + tile) * 2048) : (uint4*)0;

        #pragma unroll
        for (int half = 0; half < 2; half++) {
            float acc[8][4];
            #pragma unroll
            for (int nt = 0; nt < 8; nt++)
                #pragma unroll
                for (int q = 0; q < 4; q++) acc[nt][q] = 0.f;
            #pragma unroll
            for (int kt = 0; kt < 4; kt++) {
                uint4 ah = src[(half * 4 + kt) * 32 + lane];
                uint4 al = src[(8 + half * 4 + kt) * 32 + lane];
                #pragma unroll
                for (int nt = 0; nt < 8; nt++) {
                    uint2 bh = sBfHi[(kt * 8 + nt) * 32 + lane];
                    uint2 bl = sBfLo[(kt * 8 + nt) * 32 + lane];
                    mma16816(acc[nt], ah.x, ah.y, ah.z, ah.w, bh.x, bh.y);
                    mma16816(acc[nt], ah.x, ah.y, ah.z, ah.w, bl.x, bl.y);
                    mma16816(acc[nt], al.x, al.y, al.z, al.w, bh.x, bh.y);
                }
            }
            epilogue_half<true, (L == 1)>(acc, segs[half * 2], segs[half * 2 + 1], half,
                                          (const char*)sBG, sGBp, sAgg, lane, dst);
        }
    }
    __syncthreads();
    unsigned* gA = (L == 1 ? d_agg1 : d_agg2) + (size_t)b * 4096;
    for (int i = tid; i < 4096; i += 256) {
        unsigned v = sAgg[(i >> 6) * AGG_STR + (i & 63)];
        if (v > gA[i]) atomicMax(&gA[i], v);
    }
}

// ---------------- final: out = tile(agg2, 2) / column L2 norm ----------------
__global__ void k_final(float* __restrict__ out) {
    __shared__ float sInv[64];
    const int b = blockIdx.x, tid = threadIdx.x;
    const unsigned* agg = d_agg2 + (size_t)b * 4096;
    if (tid < 64) {
        float ss = 0.f;
        #pragma unroll 8
        for (int c = 0; c < NS; c++) {
            float v = __uint_as_float(agg[c * 64 + tid]);
            ss = fmaf(v, v, ss);
        }
        sInv[tid] = 1.0f / fmaxf(sqrtf(ss), 1e-12f);
    }
    __syncthreads();
    for (int i = tid; i < NS * 128; i += 256) {
        const int c = i >> 7, f6 = i & 63;
        out[(size_t)b * NS * 128 + i] = __uint_as_float(agg[c * 64 + f6]) * sInv[f6];
    }
}

// ---------------- launch ----------------
extern "C" void kernel_launch(void* const* d_in, const int* in_sizes, int n_in,
                              void* d_out, int out_size) {
    (void)in_sizes; (void)n_in; (void)out_size;
    const float* x  = (const float*)d_in[0];
    const void*  cl = d_in[1];
    const float* W0 = (const float*)d_in[2];
    const float* b0 = (const float*)d_in[3];
    const float* g0 = (const float*)d_in[4];
    const float* e0 = (const float*)d_in[5];
    const float* W1 = (const float*)d_in[6];
    const float* b1 = (const float*)d_in[7];
    const float* g1 = (const float*)d_in[8];
    const float* e1 = (const float*)d_in[9];
    const float* W2 = (const float*)d_in[10];
    const float* b2 = (const float*)d_in[11];
    const float* g2 = (const float*)d_in[12];
    const float* e2 = (const float*)d_in[13];
    float* out = (float*)d_out;

    static bool attr_done = false;
    if (!attr_done) {
        cudaFuncSetAttribute(k_lmma<1>, cudaFuncAttributeMaxDynamicSharedMemorySize, LT_SMEM);
        cudaFuncSetAttribute(k_lmma<2>, cudaFuncAttributeMaxDynamicSharedMemorySize, LT_SMEM);
        attr_done = true;
    }

    k_prep<<<1024, 512>>>((const int*)cl);
    k_l0<<<NB * 4, 256>>>(x, cl, W0, b0, g0, e0);
    k_lmma<1><<<NB * 4, 256, LT_SMEM>>>(cl, W1, b1, g1, e1);
    k_lmma<2><<<NB * 4, 256, LT_SMEM>>>(cl, W2, b2, g2, e2);
    k_final<<<NB, 256>>>(out);
}

// round 8
// speedup vs baseline: 2.1361x; 2.1361x over previous
#include <cuda_runtime.h>
#include <cuda_bf16.h>
#include <cstdint>
#include <cstddef>

#define NB 128
#define NT 2048
#define NS 64

// ---------------- dynamic smem layout (bytes) ----------------
#define OFF_BF1    0          // W1 B-frags (hi|lo interleaved): 2048 uint4 = 32KB
#define OFF_BF2    32768      // W2 B-frags: 32KB
#define OFF_W0P    65536      // 256 float2 = 2KB
#define OFF_GBP    67584      // 3 layers x 32 float4 = 1536B
#define OFF_BG2    69120      // 64 segs x 68 floats (permuted) = 17408B
#define OFF_AGG    86528      // 64 segs x 66 u32 = 16896B
#define OFF_INV    103424     // 64 floats
#define OFF_CL     103680     // 2048 u8 cluster ids
#define SMEM_TOTAL 105728

#define AGG_STR 66            // even (8B rows) ; bank = (2seg+c)%32, slot=(seg+tg+4nt)%16
#define BG_STR  68            // 16B chunks spread: (seg+4tg+q)%8

// permuted BG column index: f = nt*8 + tg*2 + j  ->  tg*16 + nt*2 + j
__host__ __device__ __forceinline__ int bgperm(int f) {
    return ((f & 7) >> 1) * 16 + (f >> 3) * 2 + (f & 1);
}

// ---------------- device scratch ----------------
__device__ unsigned int d_hA[(size_t)NB * 64 * 2048];   // frag images layer0->1
__device__ unsigned int d_hB[(size_t)NB * 64 * 2048];   // frag images layer1->2
__device__ int d_is32;   // .bss zero; monotone set by k_scan, idempotent across replays

// ---------------- helpers ----------------
__device__ __forceinline__ void bsplit(float v, uint32_t& h, uint32_t& l) {
    __nv_bfloat16 bh = __float2bfloat16(v);
    __nv_bfloat16 bl = __float2bfloat16(v - __bfloat162float(bh));
    h = (uint32_t)__bfloat16_as_ushort(bh);
    l = (uint32_t)__bfloat16_as_ushort(bl);
}
__device__ __forceinline__ uint32_t packbf(uint32_t lo16, uint32_t hi16) {
    return lo16 | (hi16 << 16);
}
__device__ __forceinline__ void mma16816(float* d, uint32_t a0, uint32_t a1,
                                         uint32_t a2, uint32_t a3,
                                         uint32_t b0, uint32_t b1) {
    asm volatile(
        "mma.sync.aligned.m16n8k16.row.col.f32.bf16.bf16.f32 "
        "{%0,%1,%2,%3}, {%4,%5,%6,%7}, {%8,%9}, {%0,%1,%2,%3};"
        : "+f"(d[0]), "+f"(d[1]), "+f"(d[2]), "+f"(d[3])
        : "r"(a0), "r"(a1), "r"(a2), "r"(a3), "r"(b0), "r"(b1));
}

// ---------------- cluster dtype sniff (no reset needed: monotone) ----------------
__global__ void k_scan(const int* __restrict__ cl) {
    int i = blockIdx.x * blockDim.x + threadIdx.x;
    int idx = 2 * i + 1;
    if (idx < NB * NT) { if (cl[idx] != 0) d_is32 = 1; }
}

// ---------------- shared epilogue: +BG, LN, affine, ReLU, agg, frag-store ----------------
// acc[m][nt][q]: q0=(row g+16m, col 2tg), q1=(g+16m, 2tg+1), q2=(g+8+16m, 2tg), q3=odd
__device__ __forceinline__ void epilogue(float (&acc)[2][8][4], const int* segs,
                                         int layer, char* sm, int lane,
                                         uint4* dst /* null = no frag store */) {
    const int tg = lane & 3;
    const float*  sBG  = (const float*)(sm + OFF_BG2);
    const float4* sGBp = (const float4*)(sm + OFF_GBP) + layer * 32;
    unsigned*     sAgg = (unsigned*)(sm + OFF_AGG);

    // add bias (+ gathered G) BEFORE LayerNorm — permuted table, 4x LDS.128 per row
    #pragma unroll
    for (int r = 0; r < 4; r++) {
        const int m = r >> 1, rh = r & 1;
        const float4* bgrow = (const float4*)(sBG + segs[r] * BG_STR + tg * 16);
        #pragma unroll
        for (int q = 0; q < 4; q++) {
            float4 bb = bgrow[q];
            acc[m][2 * q][rh * 2]         += bb.x;
            acc[m][2 * q][rh * 2 + 1]     += bb.y;
            acc[m][2 * q + 1][rh * 2]     += bb.z;
            acc[m][2 * q + 1][rh * 2 + 1] += bb.w;
        }
    }
    // LayerNorm stats via quad shuffles
    float mu[4], rs[4];
    #pragma unroll
    for (int r = 0; r < 4; r++) {
        const int m = r >> 1, rh = r & 1;
        float s = 0.f;
        #pragma unroll
        for (int nt = 0; nt < 8; nt++) s += acc[m][nt][rh * 2] + acc[m][nt][rh * 2 + 1];
        s += __shfl_xor_sync(0xffffffffu, s, 1);
        s += __shfl_xor_sync(0xffffffffu, s, 2);
        mu[r] = s * (1.0f / 64.0f);
        float q = 0.f;
        #pragma unroll
        for (int nt = 0; nt < 8; nt++) {
            float d0 = acc[m][nt][rh * 2]     - mu[r];
            float d1 = acc[m][nt][rh * 2 + 1] - mu[r];
            q = fmaf(d0, d0, q); q = fmaf(d1, d1, q);
        }
        q += __shfl_xor_sync(0xffffffffu, q, 1);
        q += __shfl_xor_sync(0xffffffffu, q, 2);
        rs[r] = rsqrtf(q * (1.0f / 64.0f) + 1e-5f);
    }
    // affine + relu + conditional segment max (uint2 check) + optional frag store
    #pragma unroll
    for (int m = 0; m < 2; m++) {
        #pragma unroll
        for (int ntp = 0; ntp < 4; ntp++) {
            uint32_t hi4[4], lo4[4];
            #pragma unroll
            for (int q2 = 0; q2 < 2; q2++) {
                const int nt = 2 * ntp + q2;
                float4 gb = sGBp[nt * 4 + tg];
                const int c0 = nt * 8 + tg * 2;
                #pragma unroll
                for (int rh = 0; rh < 2; rh++) {
                    const int r = m * 2 + rh;
                    float v0 = fmaxf(fmaf((acc[m][nt][rh * 2]     - mu[r]) * rs[r], gb.x, gb.y), 0.f);
                    float v1 = fmaxf(fmaf((acc[m][nt][rh * 2 + 1] - mu[r]) * rs[r], gb.z, gb.w), 0.f);
                    uint32_t u0 = __float_as_uint(v0), u1 = __float_as_uint(v1);
                    unsigned* s0 = &sAgg[segs[r] * AGG_STR + c0];
                    uint2 cur = *(const uint2*)s0;
                    if (u0 > cur.x) atomicMax(s0,     u0);
                    if (u1 > cur.y) atomicMax(s0 + 1, u1);
                    if (dst) {
                        uint32_t h0, l0, h1, l1;
                        bsplit(v0, h0, l0); bsplit(v1, h1, l1);
                        hi4[q2 * 2 + rh] = packbf(h0, h1);
                        lo4[q2 * 2 + rh] = packbf(l0, l1);
                    }
                }
            }
            if (dst) {
                dst[(m * 4 + ntp) * 32 + lane]     = *(uint4*)hi4;
                dst[(8 + m * 4 + ntp) * 32 + lane] = *(uint4*)lo4;
            }
        }
    }
}

// G[seg][f] = agg[seg] @ Wbot ; write bias_next + G into sBG (permuted cols)
__device__ __forceinline__ void make_G(const float* __restrict__ Wbot,
                                       const float* __restrict__ bnext,
                                       char* sm, int tid) {
    unsigned* sAgg = (unsigned*)(sm + OFF_AGG);
    float*    sBG  = (float*)(sm + OFF_BG2);
    const int seg = tid >> 3, f0 = (tid & 7) * 8;   // f0 = nt*8, nt = tid&7
    float a8[8];
    #pragma unroll
    for (int u = 0; u < 8; u++) a8[u] = 0.f;
    #pragma unroll 8
    for (int k = 0; k < 64; k++) {
        float av = __uint_as_float(sAgg[seg * AGG_STR + k]);
        float4 wa = __ldg((const float4*)(Wbot + k * 64 + f0));
        float4 wb = __ldg((const float4*)(Wbot + k * 64 + f0 + 4));
        a8[0] = fmaf(av, wa.x, a8[0]); a8[1] = fmaf(av, wa.y, a8[1]);
        a8[2] = fmaf(av, wa.z, a8[2]); a8[3] = fmaf(av, wa.w, a8[3]);
        a8[4] = fmaf(av, wb.x, a8[4]); a8[5] = fmaf(av, wb.y, a8[5]);
        a8[6] = fmaf(av, wb.z, a8[6]); a8[7] = fmaf(av, wb.w, a8[7]);
    }
    float* row = sBG + seg * BG_STR;
    #pragma unroll
    for (int j = 0; j < 8; j++)
        row[bgperm(f0 + j)] = bnext[f0 + j] + a8[j];
}

// ---------------- the fused kernel ----------------
__global__ __launch_bounds__(512, 1)
void k_fused(const float* __restrict__ x, const void* __restrict__ clraw,
             const float* __restrict__ W0, const float* __restrict__ bs0,
             const float* __restrict__ gm0, const float* __restrict__ bt0,
             const float* __restrict__ W1, const float* __restrict__ bs1,
             const float* __restrict__ gm1, const float* __restrict__ bt1,
             const float* __restrict__ W2, const float* __restrict__ bs2,
             const float* __restrict__ gm2, const float* __restrict__ bt2,
             float* __restrict__ out)
{
    extern __shared__ char sm[];
    uint4*         sBf1 = (uint4*)(sm + OFF_BF1);
    uint4*         sBf2 = (uint4*)(sm + OFF_BF2);
    float2*        sW0p = (float2*)(sm + OFF_W0P);
    float4*        sGBp = (float4*)(sm + OFF_GBP);
    float*         sBG  = (float*)(sm + OFF_BG2);
    unsigned*      sAgg = (unsigned*)(sm + OFF_AGG);
    float*         sInv = (float*)(sm + OFF_INV);
    unsigned char* sCl  = (unsigned char*)(sm + OFF_CL);

    const int b = blockIdx.x, tid = threadIdx.x;
    const int lane = tid & 31, warp = tid >> 5;
    const int tg = lane & 3, g = lane >> 2;

    // ---- cluster ids -> SMEM ----
    {
        const int is32 = d_is32;
        const int* c32 = (const int*)clraw;
        const long long* c64 = (const long long*)clraw;
        for (int i = tid; i < NT; i += 512) {
            int v = is32 ? c32[(size_t)b * NT + i] : (int)c64[(size_t)b * NT + i];
            sCl[i] = (unsigned char)v;
        }
    }
    // ---- build W1/W2 B-fragments, hi|lo interleaved in one uint4 ----
    for (int i = tid; i < 2048; i += 512) {
        const int l2 = i & 31, nt = (i >> 5) & 7, kt = i >> 8;
        const int tg2 = l2 & 3, g2 = l2 >> 2;
        const int k0 = kt * 16 + tg2 * 2, n = nt * 8 + g2;
        uint32_t h00, l00, h01, l01, h10, l10, h11, l11;
        bsplit(W1[k0 * 64 + n], h00, l00);       bsplit(W1[(k0 + 1) * 64 + n], h01, l01);
        bsplit(W1[(k0 + 8) * 64 + n], h10, l10); bsplit(W1[(k0 + 9) * 64 + n], h11, l11);
        sBf1[i] = make_uint4(packbf(h00, h01), packbf(h10, h11),
                             packbf(l00, l01), packbf(l10, l11));
        bsplit(W2[k0 * 64 + n], h00, l00);       bsplit(W2[(k0 + 1) * 64 + n], h01, l01);
        bsplit(W2[(k0 + 8) * 64 + n], h10, l10); bsplit(W2[(k0 + 9) * 64 + n], h11, l11);
        sBf2[i] = make_uint4(packbf(h00, h01), packbf(h10, h11),
                             packbf(l00, l01), packbf(l10, l11));
    }
    // ---- W0 in frag-col order ----
    if (tid < 256) {
        const int k = tid >> 5, nt = (tid >> 2) & 7, tg2 = tid & 3;
        const int c0 = nt * 8 + tg2 * 2;
        sW0p[tid] = make_float2(W0[k * 64 + c0], W0[k * 64 + c0 + 1]);
    }
    // ---- gamma/beta frag order for 3 layers ----
    if (tid < 96) {
        const int l = tid >> 5, p = tid & 31, nt = p >> 2, tg2 = p & 3;
        const int c0 = nt * 8 + tg2 * 2;
        const float* gl = (l == 0) ? gm0 : (l == 1) ? gm1 : gm2;
        const float* el = (l == 0) ? bt0 : (l == 1) ? bt1 : bt2;
        sGBp[tid] = make_float4(gl[c0], el[c0], gl[c0 + 1], el[c0 + 1]);
    }
    // ---- layer0 BG = bias0 replicated (permuted cols); zero agg ----
    for (int i = tid; i < NS * 64; i += 512)
        sBG[(i >> 6) * BG_STR + bgperm(i & 63)] = bs0[i & 63];
    for (int i = tid; i < NS * AGG_STR; i += 512) sAgg[i] = 0u;
    __syncthreads();

    // ================= layer 0 (scalar fp32, K=8) =================
    for (int pass = 0; pass < 4; pass++) {
        const int tile = pass * 16 + warp;
        const int tbase = tile * 32;
        float acc[2][8][4];
        #pragma unroll
        for (int m = 0; m < 2; m++)
            #pragma unroll
            for (int nt = 0; nt < 8; nt++)
                #pragma unroll
                for (int q = 0; q < 4; q++) acc[m][nt][q] = 0.f;
        float xr[4][8];
        #pragma unroll
        for (int r = 0; r < 4; r++) {
            const float4* xp = (const float4*)(x + ((size_t)b * NT + tbase + g + 8 * r) * 8);
            float4 xa = __ldg(xp), xb = __ldg(xp + 1);
            xr[r][0] = xa.x; xr[r][1] = xa.y; xr[r][2] = xa.z; xr[r][3] = xa.w;
            xr[r][4] = xb.x; xr[r][5] = xb.y; xr[r][6] = xb.z; xr[r][7] = xb.w;
        }
        #pragma unroll
        for (int k = 0; k < 8; k++) {
            #pragma unroll
            for (int nt = 0; nt < 8; nt++) {
                float2 w = sW0p[(k * 8 + nt) * 4 + tg];
                #pragma unroll
                for (int r = 0; r < 4; r++) {
                    const int m = r >> 1, rh = r & 1;
                    acc[m][nt][rh * 2]     = fmaf(xr[r][k], w.x, acc[m][nt][rh * 2]);
                    acc[m][nt][rh * 2 + 1] = fmaf(xr[r][k], w.y, acc[m][nt][rh * 2 + 1]);
                }
            }
        }
        int segs[4];
        #pragma unroll
        for (int r = 0; r < 4; r++) segs[r] = sCl[tbase + g + 8 * r];
        uint4* dst = (uint4*)(d_hA + ((size_t)b * 64 + tile) * 2048);
        epilogue(acc, segs, 0, sm, lane, dst);
    }
    __syncthreads();
    make_G(W1 + 64 * 64, bs1, sm, tid);
    __syncthreads();
    for (int i = tid; i < NS * AGG_STR; i += 512) sAgg[i] = 0u;
    __syncthreads();

    // ================= layers 1 & 2 (bf16 hi/lo mma) =================
    #pragma unroll 1
    for (int L = 1; L <= 2; L++) {
        const uint4* bf = (L == 1) ? sBf1 : sBf2;
        const unsigned int* hsrc = (L == 1) ? d_hA : d_hB;
        for (int pass = 0; pass < 4; pass++) {
            const int tile = pass * 16 + warp;
            const int tbase = tile * 32;
            const uint4* src = (const uint4*)(hsrc + ((size_t)b * 64 + tile) * 2048);
            float acc[2][8][4];
            #pragma unroll
            for (int m = 0; m < 2; m++)
                #pragma unroll
                for (int nt = 0; nt < 8; nt++)
                    #pragma unroll
                    for (int q = 0; q < 4; q++) acc[m][nt][q] = 0.f;
            #pragma unroll
            for (int kt = 0; kt < 4; kt++) {
                uint4 ah0 = src[(kt)      * 32 + lane];
                uint4 ah1 = src[(4 + kt)  * 32 + lane];
                uint4 al0 = src[(8 + kt)  * 32 + lane];
                uint4 al1 = src[(12 + kt) * 32 + lane];
                #pragma unroll
                for (int nt = 0; nt < 8; nt++) {
                    uint4 bb = bf[(kt * 8 + nt) * 32 + lane];
                    mma16816(acc[0][nt], ah0.x, ah0.y, ah0.z, ah0.w, bb.x, bb.y);
                    mma16816(acc[0][nt], ah0.x, ah0.y, ah0.z, ah0.w, bb.z, bb.w);
                    mma16816(acc[0][nt], al0.x, al0.y, al0.z, al0.w, bb.x, bb.y);
                    mma16816(acc[1][nt], ah1.x, ah1.y, ah1.z, ah1.w, bb.x, bb.y);
                    mma16816(acc[1][nt], ah1.x, ah1.y, ah1.z, ah1.w, bb.z, bb.w);
                    mma16816(acc[1][nt], al1.x, al1.y, al1.z, al1.w, bb.x, bb.y);
                }
            }
            int segs[4];
            #pragma unroll
            for (int r = 0; r < 4; r++) segs[r] = sCl[tbase + g + 8 * r];
            uint4* dst = (L == 1) ? (uint4*)(d_hB + ((size_t)b * 64 + tile) * 2048) : (uint4*)0;
            epilogue(acc, segs, L, sm, lane, dst);
        }
        __syncthreads();
        if (L == 1) {
            make_G(W2 + 64 * 64, bs2, sm, tid);
            __syncthreads();
            for (int i = tid; i < NS * AGG_STR; i += 512) sAgg[i] = 0u;
            __syncthreads();
        }
    }

    // ================= final: tile(agg,2) / column L2 norm =================
    if (tid < 64) {
        float ss = 0.f;
        #pragma unroll 8
        for (int s2 = 0; s2 < NS; s2++) {
            float v = __uint_as_float(sAgg[s2 * AGG_STR + tid]);
            ss = fmaf(v, v, ss);
        }
        sInv[tid] = 1.0f / fmaxf(sqrtf(ss), 1e-12f);
    }
    __syncthreads();
    for (int i = tid; i < NS * 128; i += 512) {
        const int s2 = i >> 7, f6 = i & 63;
        out[(size_t)b * NS * 128 + i] = __uint_as_float(sAgg[s2 * AGG_STR + f6]) * sInv[f6];
    }
}

// ---------------- launch ----------------
extern "C" void kernel_launch(void* const* d_in, const int* in_sizes, int n_in,
                              void* d_out, int out_size) {
    (void)in_sizes; (void)n_in; (void)out_size;
    const float* x  = (const float*)d_in[0];
    const void*  cl = d_in[1];
    const float* W0 = (const float*)d_in[2];
    const float* b0 = (const float*)d_in[3];
    const float* g0 = (const float*)d_in[4];
    const float* e0 = (const float*)d_in[5];
    const float* W1 = (const float*)d_in[6];
    const float* b1 = (const float*)d_in[7];
    const float* g1 = (const float*)d_in[8];
    const float* e1 = (const float*)d_in[9];
    const float* W2 = (const float*)d_in[10];
    const float* b2 = (const float*)d_in[11];
    const float* g2 = (const float*)d_in[12];
    const float* e2 = (const float*)d_in[13];
    float* out = (float*)d_out;

    static bool attr_done = false;
    if (!attr_done) {
        cudaFuncSetAttribute(k_fused, cudaFuncAttributeMaxDynamicSharedMemorySize, SMEM_TOTAL);
        attr_done = true;
    }

    k_scan<<<512, 256>>>((const int*)cl);

    k_fused<<<NB, 512, SMEM_TOTAL>>>(x, cl,
                                     W0, b0, g0, e0,
                                     W1, b1, g1, e1,
                                     W2, b2, g2, e2, out);
}

// round 9
// speedup vs baseline: 2.1376x; 1.0007x over previous
#include <cuda_runtime.h>
#include <cuda_bf16.h>
#include <cstdint>
#include <cstddef>

#define NB 128
#define NT 2048
#define NS 64

// ---------------- dynamic smem layout (bytes) ----------------
#define OFF_BF1    0          // W1 B-frags (hi|lo interleaved): 2048 uint4 = 32KB
#define OFF_BF2    32768      // W2 B-frags: 32KB
#define OFF_W0P    65536      // 256 float2 = 2KB
#define OFF_GBP    67584      // 3 layers x 32 float4 = 1536B
#define OFF_BG2    69120      // 64 segs x 68 floats (permuted) = 17408B
#define OFF_AGG    86528      // 64 segs x 66 u32 = 16896B
#define OFF_INV    103424     // 64 floats
#define OFF_CL     103680     // 2048 u8 cluster ids
#define SMEM_TOTAL 105728

#define AGG_STR 66            // even (8B rows) ; bank = (2seg+c)%32, slot=(seg+tg+4nt)%16
#define BG_STR  68            // 16B chunks spread: (seg+4tg+q)%8

// permuted BG column index: f = nt*8 + tg*2 + j  ->  tg*16 + nt*2 + j
__host__ __device__ __forceinline__ int bgperm(int f) {
    return ((f & 7) >> 1) * 16 + (f >> 3) * 2 + (f & 1);
}

// ---------------- device scratch ----------------
__device__ unsigned int d_hA[(size_t)NB * 64 * 2048];   // frag images layer0->1
__device__ unsigned int d_hB[(size_t)NB * 64 * 2048];   // frag images layer1->2
__device__ int d_is32;   // .bss zero; monotone set by k_scan, idempotent across replays

// ---------------- helpers ----------------
__device__ __forceinline__ void bsplit(float v, uint32_t& h, uint32_t& l) {
    __nv_bfloat16 bh = __float2bfloat16(v);
    __nv_bfloat16 bl = __float2bfloat16(v - __bfloat162float(bh));
    h = (uint32_t)__bfloat16_as_ushort(bh);
    l = (uint32_t)__bfloat16_as_ushort(bl);
}
__device__ __forceinline__ uint32_t packbf(uint32_t lo16, uint32_t hi16) {
    return lo16 | (hi16 << 16);
}
__device__ __forceinline__ void mma16816(float* d, uint32_t a0, uint32_t a1,
                                         uint32_t a2, uint32_t a3,
                                         uint32_t b0, uint32_t b1) {
    asm volatile(
        "mma.sync.aligned.m16n8k16.row.col.f32.bf16.bf16.f32 "
        "{%0,%1,%2,%3}, {%4,%5,%6,%7}, {%8,%9}, {%0,%1,%2,%3};"
        : "+f"(d[0]), "+f"(d[1]), "+f"(d[2]), "+f"(d[3])
        : "r"(a0), "r"(a1), "r"(a2), "r"(a3), "r"(b0), "r"(b1));
}

// ---------------- cluster dtype sniff (no reset needed: monotone) ----------------
__global__ void k_scan(const int* __restrict__ cl) {
    int i = blockIdx.x * blockDim.x + threadIdx.x;
    int idx = 2 * i + 1;
    if (idx < NB * NT) { if (cl[idx] != 0) d_is32 = 1; }
}

// ---------------- shared epilogue: +BG, LN, affine, ReLU, agg, frag-store ----------------
// acc[m][nt][q]: q0=(row g+16m, col 2tg), q1=(g+16m, 2tg+1), q2=(g+8+16m, 2tg), q3=odd
__device__ __forceinline__ void epilogue(float (&acc)[2][8][4], const int* segs,
                                         int layer, char* sm, int lane,
                                         uint4* dst /* null = no frag store */) {
    const int tg = lane & 3;
    const float*  sBG  = (const float*)(sm + OFF_BG2);
    const float4* sGBp = (const float4*)(sm + OFF_GBP) + layer * 32;
    unsigned*     sAgg = (unsigned*)(sm + OFF_AGG);

    // add bias (+ gathered G) BEFORE LayerNorm — permuted table, 4x LDS.128 per row
    #pragma unroll
    for (int r = 0; r < 4; r++) {
        const int m = r >> 1, rh = r & 1;
        const float4* bgrow = (const float4*)(sBG + segs[r] * BG_STR + tg * 16);
        #pragma unroll
        for (int q = 0; q < 4; q++) {
            float4 bb = bgrow[q];
            acc[m][2 * q][rh * 2]         += bb.x;
            acc[m][2 * q][rh * 2 + 1]     += bb.y;
            acc[m][2 * q + 1][rh * 2]     += bb.z;
            acc[m][2 * q + 1][rh * 2 + 1] += bb.w;
        }
    }
    // LayerNorm stats via quad shuffles
    float mu[4], rs[4];
    #pragma unroll
    for (int r = 0; r < 4; r++) {
        const int m = r >> 1, rh = r & 1;
        float s = 0.f;
        #pragma unroll
        for (int nt = 0; nt < 8; nt++) s += acc[m][nt][rh * 2] + acc[m][nt][rh * 2 + 1];
        s += __shfl_xor_sync(0xffffffffu, s, 1);
        s += __shfl_xor_sync(0xffffffffu, s, 2);
        mu[r] = s * (1.0f / 64.0f);
        float q = 0.f;
        #pragma unroll
        for (int nt = 0; nt < 8; nt++) {
            float d0 = acc[m][nt][rh * 2]     - mu[r];
            float d1 = acc[m][nt][rh * 2 + 1] - mu[r];
            q = fmaf(d0, d0, q); q = fmaf(d1, d1, q);
        }
        q += __shfl_xor_sync(0xffffffffu, q, 1);
        q += __shfl_xor_sync(0xffffffffu, q, 2);
        rs[r] = rsqrtf(q * (1.0f / 64.0f) + 1e-5f);
    }
    // affine + relu + conditional segment max (uint2 check) + optional frag store
    #pragma unroll
    for (int m = 0; m < 2; m++) {
        #pragma unroll
        for (int ntp = 0; ntp < 4; ntp++) {
            uint32_t hi4[4], lo4[4];
            #pragma unroll
            for (int q2 = 0; q2 < 2; q2++) {
                const int nt = 2 * ntp + q2;
                float4 gb = sGBp[nt * 4 + tg];
                const int c0 = nt * 8 + tg * 2;
                #pragma unroll
                for (int rh = 0; rh < 2; rh++) {
                    const int r = m * 2 + rh;
                    float v0 = fmaxf(fmaf((acc[m][nt][rh * 2]     - mu[r]) * rs[r], gb.x, gb.y), 0.f);
                    float v1 = fmaxf(fmaf((acc[m][nt][rh * 2 + 1] - mu[r]) * rs[r], gb.z, gb.w), 0.f);
                    uint32_t u0 = __float_as_uint(v0), u1 = __float_as_uint(v1);
                    unsigned* s0 = &sAgg[segs[r] * AGG_STR + c0];
                    uint2 cur = *(const uint2*)s0;
                    if (u0 > cur.x) atomicMax(s0,     u0);
                    if (u1 > cur.y) atomicMax(s0 + 1, u1);
                    if (dst) {
                        uint32_t h0, l0, h1, l1;
                        bsplit(v0, h0, l0); bsplit(v1, h1, l1);
                        hi4[q2 * 2 + rh] = packbf(h0, h1);
                        lo4[q2 * 2 + rh] = packbf(l0, l1);
                    }
                }
            }
            if (dst) {
                dst[(m * 4 + ntp) * 32 + lane]     = *(uint4*)hi4;
                dst[(8 + m * 4 + ntp) * 32 + lane] = *(uint4*)lo4;
            }
        }
    }
}

// G[seg][f] = agg[seg] @ Wbot ; write bias_next + G into sBG (permuted cols)
__device__ __forceinline__ void make_G(const float* __restrict__ Wbot,
                                       const float* __restrict__ bnext,
                                       char* sm, int tid) {
    unsigned* sAgg = (unsigned*)(sm + OFF_AGG);
    float*    sBG  = (float*)(sm + OFF_BG2);
    const int seg = tid >> 3, f0 = (tid & 7) * 8;   // f0 = nt*8, nt = tid&7
    float a8[8];
    #pragma unroll
    for (int u = 0; u < 8; u++) a8[u] = 0.f;
    #pragma unroll 8
    for (int k = 0; k < 64; k++) {
        float av = __uint_as_float(sAgg[seg * AGG_STR + k]);
        float4 wa = __ldg((const float4*)(Wbot + k * 64 + f0));
        float4 wb = __ldg((const float4*)(Wbot + k * 64 + f0 + 4));
        a8[0] = fmaf(av, wa.x, a8[0]); a8[1] = fmaf(av, wa.y, a8[1]);
        a8[2] = fmaf(av, wa.z, a8[2]); a8[3] = fmaf(av, wa.w, a8[3]);
        a8[4] = fmaf(av, wb.x, a8[4]); a8[5] = fmaf(av, wb.y, a8[5]);
        a8[6] = fmaf(av, wb.z, a8[6]); a8[7] = fmaf(av, wb.w, a8[7]);
    }
    float* row = sBG + seg * BG_STR;
    #pragma unroll
    for (int j = 0; j < 8; j++)
        row[bgperm(f0 + j)] = bnext[f0 + j] + a8[j];
}

// ---------------- the fused kernel ----------------
__global__ __launch_bounds__(512, 1)
void k_fused(const float* __restrict__ x, const void* __restrict__ clraw,
             const float* __restrict__ W0, const float* __restrict__ bs0,
             const float* __restrict__ gm0, const float* __restrict__ bt0,
             const float* __restrict__ W1, const float* __restrict__ bs1,
             const float* __restrict__ gm1, const float* __restrict__ bt1,
             const float* __restrict__ W2, const float* __restrict__ bs2,
             const float* __restrict__ gm2, const float* __restrict__ bt2,
             float* __restrict__ out)
{
    extern __shared__ char sm[];
    uint4*         sBf1 = (uint4*)(sm + OFF_BF1);
    uint4*         sBf2 = (uint4*)(sm + OFF_BF2);
    float2*        sW0p = (float2*)(sm + OFF_W0P);
    float4*        sGBp = (float4*)(sm + OFF_GBP);
    float*         sBG  = (float*)(sm + OFF_BG2);
    unsigned*      sAgg = (unsigned*)(sm + OFF_AGG);
    float*         sInv = (float*)(sm + OFF_INV);
    unsigned char* sCl  = (unsigned char*)(sm + OFF_CL);

    const int b = blockIdx.x, tid = threadIdx.x;
    const int lane = tid & 31, warp = tid >> 5;
    const int tg = lane & 3, g = lane >> 2;

    // ---- cluster ids -> SMEM ----
    {
        const int is32 = d_is32;
        const int* c32 = (const int*)clraw;
        const long long* c64 = (const long long*)clraw;
        for (int i = tid; i < NT; i += 512) {
            int v = is32 ? c32[(size_t)b * NT + i] : (int)c64[(size_t)b * NT + i];
            sCl[i] = (unsigned char)v;
        }
    }
    // ---- build W1/W2 B-fragments, hi|lo interleaved in one uint4 ----
    for (int i = tid; i < 2048; i += 512) {
        const int l2 = i & 31, nt = (i >> 5) & 7, kt = i >> 8;
        const int tg2 = l2 & 3, g2 = l2 >> 2;
        const int k0 = kt * 16 + tg2 * 2, n = nt * 8 + g2;
        uint32_t h00, l00, h01, l01, h10, l10, h11, l11;
        bsplit(W1[k0 * 64 + n], h00, l00);       bsplit(W1[(k0 + 1) * 64 + n], h01, l01);
        bsplit(W1[(k0 + 8) * 64 + n], h10, l10); bsplit(W1[(k0 + 9) * 64 + n], h11, l11);
        sBf1[i] = make_uint4(packbf(h00, h01), packbf(h10, h11),
                             packbf(l00, l01), packbf(l10, l11));
        bsplit(W2[k0 * 64 + n], h00, l00);       bsplit(W2[(k0 + 1) * 64 + n], h01, l01);
        bsplit(W2[(k0 + 8) * 64 + n], h10, l10); bsplit(W2[(k0 + 9) * 64 + n], h11, l11);
        sBf2[i] = make_uint4(packbf(h00, h01), packbf(h10, h11),
                             packbf(l00, l01), packbf(l10, l11));
    }
    // ---- W0 in frag-col order ----
    if (tid < 256) {
        const int k = tid >> 5, nt = (tid >> 2) & 7, tg2 = tid & 3;
        const int c0 = nt * 8 + tg2 * 2;
        sW0p[tid] = make_float2(W0[k * 64 + c0], W0[k * 64 + c0 + 1]);
    }
    // ---- gamma/beta frag order for 3 layers ----
    if (tid < 96) {
        const int l = tid >> 5, p = tid & 31, nt = p >> 2, tg2 = p & 3;
        const int c0 = nt * 8 + tg2 * 2;
        const float* gl = (l == 0) ? gm0 : (l == 1) ? gm1 : gm2;
        const float* el = (l == 0) ? bt0 : (l == 1) ? bt1 : bt2;
        sGBp[tid] = make_float4(gl[c0], el[c0], gl[c0 + 1], el[c0 + 1]);
    }
    // ---- layer0 BG = bias0 replicated (permuted cols); zero agg ----
    for (int i = tid; i < NS * 64; i += 512)
        sBG[(i >> 6) * BG_STR + bgperm(i & 63)] = bs0[i & 63];
    for (int i = tid; i < NS * AGG_STR; i += 512) sAgg[i] = 0u;
    __syncthreads();

    // ================= layer 0 (scalar fp32, K=8) =================
    for (int pass = 0; pass < 4; pass++) {
        const int tile = pass * 16 + warp;
        const int tbase = tile * 32;
        float acc[2][8][4];
        #pragma unroll
        for (int m = 0; m < 2; m++)
            #pragma unroll
            for (int nt = 0; nt < 8; nt++)
                #pragma unroll
                for (int q = 0; q < 4; q++) acc[m][nt][q] = 0.f;
        float xr[4][8];
        #pragma unroll
        for (int r = 0; r < 4; r++) {
            const float4* xp = (const float4*)(x + ((size_t)b * NT + tbase + g + 8 * r) * 8);
            float4 xa = __ldg(xp), xb = __ldg(xp + 1);
            xr[r][0] = xa.x; xr[r][1] = xa.y; xr[r][2] = xa.z; xr[r][3] = xa.w;
            xr[r][4] = xb.x; xr[r][5] = xb.y; xr[r][6] = xb.z; xr[r][7] = xb.w;
        }
        #pragma unroll
        for (int k = 0; k < 8; k++) {
            #pragma unroll
            for (int nt = 0; nt < 8; nt++) {
                float2 w = sW0p[(k * 8 + nt) * 4 + tg];
                #pragma unroll
                for (int r = 0; r < 4; r++) {
                    const int m = r >> 1, rh = r & 1;
                    acc[m][nt][rh * 2]     = fmaf(xr[r][k], w.x, acc[m][nt][rh * 2]);
                    acc[m][nt][rh * 2 + 1] = fmaf(xr[r][k], w.y, acc[m][nt][rh * 2 + 1]);
                }
            }
        }
        int segs[4];
        #pragma unroll
        for (int r = 0; r < 4; r++) segs[r] = sCl[tbase + g + 8 * r];
        uint4* dst = (uint4*)(d_hA + ((size_t)b * 64 + tile) * 2048);
        epilogue(acc, segs, 0, sm, lane, dst);
    }
    __syncthreads();
    make_G(W1 + 64 * 64, bs1, sm, tid);
    __syncthreads();
    for (int i = tid; i < NS * AGG_STR; i += 512) sAgg[i] = 0u;
    __syncthreads();

    // ================= layers 1 & 2 (bf16 hi/lo mma) =================
    #pragma unroll 1
    for (int L = 1; L <= 2; L++) {
        const uint4* bf = (L == 1) ? sBf1 : sBf2;
        const unsigned int* hsrc = (L == 1) ? d_hA : d_hB;
        for (int pass = 0; pass < 4; pass++) {
            const int tile = pass * 16 + warp;
            const int tbase = tile * 32;
            const uint4* src = (const uint4*)(hsrc + ((size_t)b * 64 + tile) * 2048);
            float acc[2][8][4];
            #pragma unroll
            for (int m = 0; m < 2; m++)
                #pragma unroll
                for (int nt = 0; nt < 8; nt++)
                    #pragma unroll
                    for (int q = 0; q < 4; q++) acc[m][nt][q] = 0.f;
            #pragma unroll
            for (int kt = 0; kt < 4; kt++) {
                uint4 ah0 = src[(kt)      * 32 + lane];
                uint4 ah1 = src[(4 + kt)  * 32 + lane];
                uint4 al0 = src[(8 + kt)  * 32 + lane];
                uint4 al1 = src[(12 + kt) * 32 + lane];
                #pragma unroll
                for (int nt = 0; nt < 8; nt++) {
                    uint4 bb = bf[(kt * 8 + nt) * 32 + lane];
                    mma16816(acc[0][nt], ah0.x, ah0.y, ah0.z, ah0.w, bb.x, bb.y);
                    mma16816(acc[0][nt], ah0.x, ah0.y, ah0.z, ah0.w, bb.z, bb.w);
                    mma16816(acc[0][nt], al0.x, al0.y, al0.z, al0.w, bb.x, bb.y);
                    mma16816(acc[1][nt], ah1.x, ah1.y, ah1.z, ah1.w, bb.x, bb.y);
                    mma16816(acc[1][nt], ah1.x, ah1.y, ah1.z, ah1.w, bb.z, bb.w);
                    mma16816(acc[1][nt], al1.x, al1.y, al1.z, al1.w, bb.x, bb.y);
                }
            }
            int segs[4];
            #pragma unroll
            for (int r = 0; r < 4; r++) segs[r] = sCl[tbase + g + 8 * r];
            uint4* dst = (L == 1) ? (uint4*)(d_hB + ((size_t)b * 64 + tile) * 2048) : (uint4*)0;
            epilogue(acc, segs, L, sm, lane, dst);
        }
        __syncthreads();
        if (L == 1) {
            make_G(W2 + 64 * 64, bs2, sm, tid);
            __syncthreads();
            for (int i = tid; i < NS * AGG_STR; i += 512) sAgg[i] = 0u;
            __syncthreads();
        }
    }

    // ================= final: tile(agg,2) / column L2 norm =================
    if (tid < 64) {
        float ss = 0.f;
        #pragma unroll 8
        for (int s2 = 0; s2 < NS; s2++) {
            float v = __uint_as_float(sAgg[s2 * AGG_STR + tid]);
            ss = fmaf(v, v, ss);
        }
        sInv[tid] = 1.0f / fmaxf(sqrtf(ss), 1e-12f);
    }
    __syncthreads();
    for (int i = tid; i < NS * 128; i += 512) {
        const int s2 = i >> 7, f6 = i & 63;
        out[(size_t)b * NS * 128 + i] = __uint_as_float(sAgg[s2 * AGG_STR + f6]) * sInv[f6];
    }
}

// ---------------- launch ----------------
extern "C" void kernel_launch(void* const* d_in, const int* in_sizes, int n_in,
                              void* d_out, int out_size) {
    (void)in_sizes; (void)n_in; (void)out_size;
    const float* x  = (const float*)d_in[0];
    const void*  cl = d_in[1];
    const float* W0 = (const float*)d_in[2];
    const float* b0 = (const float*)d_in[3];
    const float* g0 = (const float*)d_in[4];
    const float* e0 = (const float*)d_in[5];
    const float* W1 = (const float*)d_in[6];
    const float* b1 = (const float*)d_in[7];
    const float* g1 = (const float*)d_in[8];
    const float* e1 = (const float*)d_in[9];
    const float* W2 = (const float*)d_in[10];
    const float* b2 = (const float*)d_in[11];
    const float* g2 = (const float*)d_in[12];
    const float* e2 = (const float*)d_in[13];
    float* out = (float*)d_out;

    static bool attr_done = false;
    if (!attr_done) {
        cudaFuncSetAttribute(k_fused, cudaFuncAttributeMaxDynamicSharedMemorySize, SMEM_TOTAL);
        attr_done = true;
    }

    k_scan<<<512, 256>>>((const int*)cl);

    k_fused<<<NB, 512, SMEM_TOTAL>>>(x, cl,
                                     W0, b0, g0, e0,
                                     W1, b1, g1, e1,
                                     W2, b2, g2, e2, out);
}